// round 8
// baseline (speedup 1.0000x reference)
#include <cuda_runtime.h>

#define DD 24
#define HH 48
#define WW 64
#define NV (DD*HH*WW)        /* 73728 interior voxels */
#define CIN 32
#define COUT 48
#define OHALF 24             /* channels per qkv block (gridDim.y = 2) */

#define TD 4
#define TH 8
#define SROW 68                        /* padded smem row stride (floats) */
#define NROWS ((TD+2)*(TH+2))          /* 60 */
#define TCOL 66                        /* loaded cols per smem row (w=-1..64) */

// scratch (allocation-free rule: __device__ globals)
__device__ float g_q[COUT * NV];
__device__ float g_k[COUT * NV];
__device__ float g_v[COUT * NV];

typedef unsigned long long u64;
__device__ __forceinline__ u64 fma2(u64 a, u64 b, u64 c) {
    u64 d; asm("fma.rn.f32x2 %0,%1,%2,%3;" : "=l"(d) : "l"(a), "l"(b), "l"(c));
    return d;
}
__device__ __forceinline__ u64 add2(u64 a, u64 b) {
    u64 d; asm("add.rn.f32x2 %0,%1,%2;" : "=l"(d) : "l"(a), "l"(b));
    return d;
}
__device__ __forceinline__ u64 mul2(u64 a, u64 b) {
    u64 d; asm("mul.rn.f32x2 %0,%1,%2;" : "=l"(d) : "l"(a), "l"(b));
    return d;
}
__device__ __forceinline__ u64 pack2(float lo, float hi) {
    u64 r; asm("mov.b64 %0,{%1,%2};" : "=l"(r) : "f"(lo), "f"(hi)); return r;
}
__device__ __forceinline__ void unpack2(u64 p, float& lo, float& hi) {
    asm("mov.b64 {%0,%1},%2;" : "=f"(lo), "=f"(hi) : "l"(p));
}
__device__ __forceinline__ float ex2f(float x) {
    float y; asm("ex2.approx.ftz.f32 %0, %1;" : "=f"(y) : "f"(x)); return y;
}
__device__ __forceinline__ float rcpf(float x) {
    float y; asm("rcp.approx.ftz.f32 %0, %1;" : "=f"(y) : "f"(x)); return y;
}

// ---------------------------------------------------------------------------
// Fused QKV (frozen at measured ~21us): one thread = one voxel pair x 24
// channels; packed f32x2 math, LDS.128 weights.
// ---------------------------------------------------------------------------
__global__ __launch_bounds__(256)
void qkv_kernel(const float* __restrict__ x,
                const float* __restrict__ Wq,
                const float* __restrict__ Wk,
                const float* __restrict__ Wv) {
    __shared__ u64 swq[OHALF * CIN];
    __shared__ u64 swk[OHALF * CIN];
    __shared__ u64 swv[OHALF * CIN];

    const int ob = blockIdx.y * OHALF;
    for (int i = threadIdx.x; i < OHALF * CIN; i += 256) {
        const int gi = ob * CIN + i;
        float a = Wq[gi], b = Wk[gi], c = Wv[gi];
        u64 pa, pb, pc;
        asm("mov.b64 %0,{%1,%1};" : "=l"(pa) : "f"(a));
        asm("mov.b64 %0,{%1,%1};" : "=l"(pb) : "f"(b));
        asm("mov.b64 %0,{%1,%1};" : "=l"(pc) : "f"(c));
        swq[i] = pa; swk[i] = pb; swv[i] = pc;
    }
    __syncthreads();

    const int t = blockIdx.x * 256 + threadIdx.x;   // 0..36863
    const int v0 = t * 2;

    u64 xs[CIN];
    #pragma unroll
    for (int c = 0; c < CIN; c++)
        xs[c] = *(const u64*)(x + c * NV + v0);

    float* __restrict__ gq = g_q + ob * NV + v0;
    float* __restrict__ gk = g_k + ob * NV + v0;
    float* __restrict__ gv = g_v + ob * NV + v0;

    #pragma unroll 4
    for (int o = 0; o < OHALF; o++) {
        u64 qa = 0, qb = 0, ka = 0, kb = 0, va = 0, vb = 0;
        #pragma unroll
        for (int c = 0; c < CIN; c += 2) {
            const u64 x0 = xs[c], x1 = xs[c + 1];
            const ulonglong2 wq = *(const ulonglong2*)&swq[o * CIN + c];
            const ulonglong2 wk = *(const ulonglong2*)&swk[o * CIN + c];
            const ulonglong2 wv = *(const ulonglong2*)&swv[o * CIN + c];
            qa = fma2(wq.x, x0, qa);  qb = fma2(wq.y, x1, qb);
            ka = fma2(wk.x, x0, ka);  kb = fma2(wk.y, x1, kb);
            va = fma2(wv.x, x0, va);  vb = fma2(wv.y, x1, vb);
        }
        *(u64*)(gq + o * NV) = add2(qa, qb);
        *(u64*)(gk + o * NV) = add2(ka, kb);
        *(u64*)(gv + o * NV) = add2(va, vb);
    }
}

// ---------------------------------------------------------------------------
// Pass 2: per-channel attention, 4 outputs/thread, f32x2-packed tap loop.
// ---------------------------------------------------------------------------
template<int GRP>
__device__ __forceinline__ void attn_core(const float* __restrict__ sk,
                                          const float* __restrict__ sv,
                                          u64 qp0, u64 qp1,
                                          const u64 qba[3], const u64 qbb[3],
                                          int rbase, int w0,
                                          u64& dena, u64& denb,
                                          u64& numa, u64& numb) {
    #pragma unroll
    for (int kd = 0; kd < 3; kd++) {
        #pragma unroll
        for (int kh = 0; kh < 3; kh++) {
            const int rb = rbase + (kd * (TH + 2) + kh) * SROW + w0;
            const float4 ka4 = *(const float4*)(sk + rb);
            const float2 kc2 = *(const float2*)(sk + rb + 4);
            const float4 va4 = *(const float4*)(sv + rb);
            const float2 vc2 = *(const float2*)(sv + rb + 4);
            const float kk[6] = {ka4.x, ka4.y, ka4.z, ka4.w, kc2.x, kc2.y};
            const float vv[6] = {va4.x, va4.y, va4.z, va4.w, vc2.x, vc2.y};
            #pragma unroll
            for (int kw = 0; kw < 3; kw++) {
                const int sel = (GRP == 0) ? kw : ((GRP == 1) ? kd : kh);
                const u64 kpa = pack2(kk[kw], kk[kw + 1]);
                const u64 kpb = pack2(kk[kw + 2], kk[kw + 3]);
                const u64 vpa = pack2(vv[kw], vv[kw + 1]);
                const u64 vpb = pack2(vv[kw + 2], vv[kw + 3]);
                const u64 arga = fma2(qp0, kpa, qba[sel]);
                const u64 argb = fma2(qp1, kpb, qbb[sel]);
                float a0, a1, a2, a3;
                unpack2(arga, a0, a1);
                unpack2(argb, a2, a3);
                const u64 epa = pack2(ex2f(a0), ex2f(a1));
                const u64 epb = pack2(ex2f(a2), ex2f(a3));
                dena = add2(dena, epa);
                denb = add2(denb, epb);
                numa = fma2(epa, vpa, numa);
                numb = fma2(epb, vpb, numb);
            }
        }
    }
}

__global__ __launch_bounds__(512)
void attn_kernel(const float* __restrict__ rel_h,
                 const float* __restrict__ rel_w,
                 const float* __restrict__ rel_d,
                 float* __restrict__ out) {
    __shared__ float sk[NROWS * SROW];
    __shared__ float sv[NROWS * SROW];

    const int o  = blockIdx.z;
    const int d0 = blockIdx.x * TD;
    const int h0 = blockIdx.y * TH;
    const int tid = threadIdx.x + (threadIdx.y << 4) + (threadIdx.z << 7);

    // ---- hoisted gmem loads (overlap with halo fill) ----
    const int w0 = threadIdx.x << 2;
    const int hl = threadIdx.y;
    const int dl = threadIdx.z;
    const int vox0 = ((d0 + dl) * HH + (h0 + hl)) * WW + w0;

    const float4 q4 = *(const float4*)(g_q + o * NV + vox0);
    const int grp = o >> 4, ci = o & 15;
    const float* rel = (grp == 0) ? (rel_d + ci * 3)
                     : (grp == 1) ? (rel_h + ci * 3)
                                  : (rel_w + ci * 3);
    const float b0 = rel[0], b1 = rel[1], b2 = rel[2];

    const float L2E = 1.4426950408889634f;
    const u64 qp0 = pack2(q4.x * L2E, q4.y * L2E);
    const u64 qp1 = pack2(q4.z * L2E, q4.w * L2E);
    u64 qba[3], qbb[3];
    qba[0] = mul2(qp0, pack2(b0, b0));  qbb[0] = mul2(qp1, pack2(b0, b0));
    qba[1] = mul2(qp0, pack2(b1, b1));  qbb[1] = mul2(qp1, pack2(b1, b1));
    qba[2] = mul2(qp0, pack2(b2, b2));  qbb[2] = mul2(qp1, pack2(b2, b2));

    // ---- cooperative halo load (zeros outside interior) ----
    const int cbase = o * NV;
    for (int i = tid; i < NROWS * TCOL; i += 512) {
        const int row = i / TCOL;          // 0..59
        const int col = i - row * TCOL;    // 0..65
        const int dd  = row / (TH + 2);    // 0..5
        const int hh  = row - dd * (TH + 2);
        const int d = d0 + dd - 1;
        const int h = h0 + hh - 1;
        const int w = col - 1;
        const bool ok = ((unsigned)d < DD) & ((unsigned)h < HH) & ((unsigned)w < WW);
        float kv = 0.f, vv = 0.f;
        if (ok) {
            const int g = cbase + (d * HH + h) * WW + w;
            kv = g_k[g];
            vv = g_v[g];
        }
        const int s = row * SROW + col;
        sk[s] = kv;
        sv[s] = vv;
    }
    __syncthreads();

    const int rbase = (dl * (TH + 2) + hl) * SROW;

    u64 dena = 0, denb = 0, numa = 0, numb = 0;

    if (grp == 0)      attn_core<0>(sk, sv, qp0, qp1, qba, qbb, rbase, w0, dena, denb, numa, numb);
    else if (grp == 1) attn_core<1>(sk, sv, qp0, qp1, qba, qbb, rbase, w0, dena, denb, numa, numb);
    else               attn_core<2>(sk, sv, qp0, qp1, qba, qbb, rbase, w0, dena, denb, numa, numb);

    float d0f, d1f, d2f, d3f, n0f, n1f, n2f, n3f;
    unpack2(dena, d0f, d1f);
    unpack2(denb, d2f, d3f);
    unpack2(numa, n0f, n1f);
    unpack2(numb, n2f, n3f);

    float4 r;
    r.x = n0f * rcpf(d0f);
    r.y = n1f * rcpf(d1f);
    r.z = n2f * rcpf(d2f);
    r.w = n3f * rcpf(d3f);
    *(float4*)(out + o * NV + vox0) = r;
}

extern "C" void kernel_launch(void* const* d_in, const int* in_sizes, int n_in,
                              void* d_out, int out_size) {
    const float* x     = (const float*)d_in[0];
    const float* Wq    = (const float*)d_in[1];
    const float* Wk    = (const float*)d_in[2];
    const float* Wv    = (const float*)d_in[3];
    const float* rel_h = (const float*)d_in[4];
    const float* rel_w = (const float*)d_in[5];
    const float* rel_d = (const float*)d_in[6];
    float* out = (float*)d_out;

    dim3 g1(NV / 2 / 256, 2);
    qkv_kernel<<<g1, 256>>>(x, Wq, Wk, Wv);

    dim3 g2(DD / TD, HH / TH, COUT);
    dim3 b2(16, TH, TD);
    attn_kernel<<<g2, b2>>>(rel_h, rel_w, rel_d, out);
}

// round 9
// speedup vs baseline: 1.3979x; 1.3979x over previous
#include <cuda_runtime.h>

#define DD 24
#define HH 48
#define WW 64
#define NV (DD*HH*WW)        /* 73728 interior voxels */
#define CIN 32
#define COUT 48

#define TD 4
#define TH 8
#define SROW 68                        /* padded smem row stride (floats) */
#define NROWS ((TD+2)*(TH+2))          /* 60 */
#define TCOL 66                        /* loaded cols per smem row (w=-1..64) */

// scratch (allocation-free rule: __device__ globals)
__device__ float g_q[COUT * NV];
__device__ float g_k[COUT * NV];
__device__ float g_v[COUT * NV];

typedef unsigned long long u64;
__device__ __forceinline__ u64 fma2(u64 a, u64 b, u64 c) {
    u64 d; asm("fma.rn.f32x2 %0,%1,%2,%3;" : "=l"(d) : "l"(a), "l"(b), "l"(c));
    return d;
}
__device__ __forceinline__ u64 add2(u64 a, u64 b) {
    u64 d; asm("add.rn.f32x2 %0,%1,%2;" : "=l"(d) : "l"(a), "l"(b));
    return d;
}
__device__ __forceinline__ float ex2f(float x) {
    float y; asm("ex2.approx.ftz.f32 %0, %1;" : "=f"(y) : "f"(x)); return y;
}
__device__ __forceinline__ float rcpf(float x) {
    float y; asm("rcp.approx.ftz.f32 %0, %1;" : "=f"(y) : "f"(x)); return y;
}

// ---------------------------------------------------------------------------
// Fused QKV (R6-measured structure): one thread = one voxel pair x NCH
// channels starting at obase; packed f32x2 math, LDS.128 weights.
// ---------------------------------------------------------------------------
template<int NCH>
__global__ __launch_bounds__(256)
void qkv_kernel(const float* __restrict__ x,
                const float* __restrict__ Wq,
                const float* __restrict__ Wk,
                const float* __restrict__ Wv,
                int obase) {
    __shared__ u64 swq[NCH * CIN];
    __shared__ u64 swk[NCH * CIN];
    __shared__ u64 swv[NCH * CIN];

    for (int i = threadIdx.x; i < NCH * CIN; i += 256) {
        const int gi = obase * CIN + i;
        float a = Wq[gi], b = Wk[gi], c = Wv[gi];
        u64 pa, pb, pc;
        asm("mov.b64 %0,{%1,%1};" : "=l"(pa) : "f"(a));
        asm("mov.b64 %0,{%1,%1};" : "=l"(pb) : "f"(b));
        asm("mov.b64 %0,{%1,%1};" : "=l"(pc) : "f"(c));
        swq[i] = pa; swk[i] = pb; swv[i] = pc;
    }
    __syncthreads();

    const int t = blockIdx.x * 256 + threadIdx.x;   // 0..36863
    const int v0 = t * 2;

    u64 xs[CIN];
    #pragma unroll
    for (int c = 0; c < CIN; c++)
        xs[c] = *(const u64*)(x + c * NV + v0);

    float* __restrict__ gq = g_q + obase * NV + v0;
    float* __restrict__ gk = g_k + obase * NV + v0;
    float* __restrict__ gv = g_v + obase * NV + v0;

    #pragma unroll 4
    for (int o = 0; o < NCH; o++) {
        u64 qa = 0, qb = 0, ka = 0, kb = 0, va = 0, vb = 0;
        #pragma unroll
        for (int c = 0; c < CIN; c += 2) {
            const u64 x0 = xs[c], x1 = xs[c + 1];
            const ulonglong2 wq = *(const ulonglong2*)&swq[o * CIN + c];
            const ulonglong2 wk = *(const ulonglong2*)&swk[o * CIN + c];
            const ulonglong2 wv = *(const ulonglong2*)&swv[o * CIN + c];
            qa = fma2(wq.x, x0, qa);  qb = fma2(wq.y, x1, qb);
            ka = fma2(wk.x, x0, ka);  kb = fma2(wk.y, x1, kb);
            va = fma2(wv.x, x0, va);  vb = fma2(wv.y, x1, vb);
        }
        *(u64*)(gq + o * NV) = add2(qa, qb);
        *(u64*)(gk + o * NV) = add2(ka, kb);
        *(u64*)(gv + o * NV) = add2(va, vb);
    }
}

// ---------------------------------------------------------------------------
// Pass 2 (exact R7 scalar core, measured 39.3us): per-channel attention,
// 4 outputs/thread, tile 4x8x64 (512 threads); channel = obase + blockIdx.z.
// ---------------------------------------------------------------------------
template<int GRP>
__device__ __forceinline__ void attn_core(const float* __restrict__ sk,
                                          const float* __restrict__ sv,
                                          const float qs[4],
                                          const float qb[3][4],
                                          int rbase, int w0,
                                          float num[4], float den[4]) {
    #pragma unroll
    for (int kd = 0; kd < 3; kd++) {
        #pragma unroll
        for (int kh = 0; kh < 3; kh++) {
            const int rb = rbase + (kd * (TH + 2) + kh) * SROW + w0;
            const float4 ka = *(const float4*)(sk + rb);
            const float2 kc = *(const float2*)(sk + rb + 4);
            const float4 va = *(const float4*)(sv + rb);
            const float2 vc = *(const float2*)(sv + rb + 4);
            const float kk[6] = {ka.x, ka.y, ka.z, ka.w, kc.x, kc.y};
            const float vv[6] = {va.x, va.y, va.z, va.w, vc.x, vc.y};
            #pragma unroll
            for (int kw = 0; kw < 3; kw++) {
                const int sel = (GRP == 0) ? kw : ((GRP == 1) ? kd : kh);
                #pragma unroll
                for (int wi = 0; wi < 4; wi++) {
                    const float arg = fmaf(qs[wi], kk[wi + kw], qb[sel][wi]);
                    const float ex  = ex2f(arg);
                    den[wi] += ex;
                    num[wi] = fmaf(ex, vv[wi + kw], num[wi]);
                }
            }
        }
    }
}

__global__ __launch_bounds__(512, 3)
void attn_kernel(const float* __restrict__ rel_h,
                 const float* __restrict__ rel_w,
                 const float* __restrict__ rel_d,
                 float* __restrict__ out,
                 int obase) {
    __shared__ float sk[NROWS * SROW];
    __shared__ float sv[NROWS * SROW];

    const int o  = obase + blockIdx.z;
    const int d0 = blockIdx.x * TD;
    const int h0 = blockIdx.y * TH;
    const int tid = threadIdx.x + (threadIdx.y << 4) + (threadIdx.z << 7);

    // ---- hoisted gmem loads (overlap with halo fill) ----
    const int w0 = threadIdx.x << 2;
    const int hl = threadIdx.y;
    const int dl = threadIdx.z;
    const int vox0 = ((d0 + dl) * HH + (h0 + hl)) * WW + w0;

    const float4 q4 = *(const float4*)(g_q + o * NV + vox0);
    const int grp = o >> 4, ci = o & 15;
    const float* rel = (grp == 0) ? (rel_d + ci * 3)
                     : (grp == 1) ? (rel_h + ci * 3)
                                  : (rel_w + ci * 3);
    const float b0 = rel[0], b1 = rel[1], b2 = rel[2];

    const float L2E = 1.4426950408889634f;
    float qs[4] = {q4.x * L2E, q4.y * L2E, q4.z * L2E, q4.w * L2E};
    float qb[3][4];
    #pragma unroll
    for (int wi = 0; wi < 4; wi++) {
        qb[0][wi] = qs[wi] * b0;
        qb[1][wi] = qs[wi] * b1;
        qb[2][wi] = qs[wi] * b2;
    }

    // ---- cooperative halo load (zeros outside interior) ----
    const int cbase = o * NV;
    for (int i = tid; i < NROWS * TCOL; i += 512) {
        const int row = i / TCOL;          // 0..59
        const int col = i - row * TCOL;    // 0..65
        const int dd  = row / (TH + 2);    // 0..5
        const int hh  = row - dd * (TH + 2);
        const int d = d0 + dd - 1;
        const int h = h0 + hh - 1;
        const int w = col - 1;
        const bool ok = ((unsigned)d < DD) & ((unsigned)h < HH) & ((unsigned)w < WW);
        float kv = 0.f, vv = 0.f;
        if (ok) {
            const int g = cbase + (d * HH + h) * WW + w;
            kv = g_k[g];
            vv = g_v[g];
        }
        const int s = row * SROW + col;
        sk[s] = kv;
        sv[s] = vv;
    }
    __syncthreads();

    const int rbase = (dl * (TH + 2) + hl) * SROW;

    float num[4] = {0.f, 0.f, 0.f, 0.f};
    float den[4] = {0.f, 0.f, 0.f, 0.f};

    if (grp == 0)      attn_core<0>(sk, sv, qs, qb, rbase, w0, num, den);
    else if (grp == 1) attn_core<1>(sk, sv, qs, qb, rbase, w0, num, den);
    else               attn_core<2>(sk, sv, qs, qb, rbase, w0, num, den);

    float4 r;
    r.x = num[0] * rcpf(den[0]);
    r.y = num[1] * rcpf(den[1]);
    r.z = num[2] * rcpf(den[2]);
    r.w = num[3] * rcpf(den[3]);
    *(float4*)(out + o * NV + vox0) = r;
}

extern "C" void kernel_launch(void* const* d_in, const int* in_sizes, int n_in,
                              void* d_out, int out_size) {
    const float* x     = (const float*)d_in[0];
    const float* Wq    = (const float*)d_in[1];
    const float* Wk    = (const float*)d_in[2];
    const float* Wv    = (const float*)d_in[3];
    const float* rel_h = (const float*)d_in[4];
    const float* rel_w = (const float*)d_in[5];
    const float* rel_d = (const float*)d_in[6];
    float* out = (float*)d_out;

    // Lazily-created side stream + fork/join events (created on the first,
    // uncaptured, correctness call; only launches/event nodes are captured).
    static cudaStream_t s2 = (cudaStream_t)0;
    static cudaEvent_t eFork = (cudaEvent_t)0, eJoin = (cudaEvent_t)0;
    static int ready = 0;
    if (!ready) {
        cudaStream_t ts; cudaEvent_t t1, t2;
        if (cudaStreamCreateWithFlags(&ts, cudaStreamNonBlocking) == cudaSuccess &&
            cudaEventCreateWithFlags(&t1, cudaEventDisableTiming) == cudaSuccess &&
            cudaEventCreateWithFlags(&t2, cudaEventDisableTiming) == cudaSuccess) {
            s2 = ts; eFork = t1; eJoin = t2; ready = 1;
        } else {
            ready = -1;   // fall back to single stream
        }
    }

    dim3 b2(16, TH, TD);

    if (ready == 1) {
        cudaEventRecord(eFork, 0);
        cudaStreamWaitEvent(s2, eFork, 0);

        // stream 0: 32-channel half (long pole, starts immediately)
        qkv_kernel<32><<<NV / 2 / 256, 256>>>(x, Wq, Wk, Wv, 0);
        attn_kernel<<<dim3(DD / TD, HH / TH, 32), b2>>>(rel_h, rel_w, rel_d, out, 0);

        // stream s2: 16-channel half (finishes qkv early -> attnB overlaps qkvA tail)
        qkv_kernel<16><<<NV / 2 / 256, 256, 0, s2>>>(x, Wq, Wk, Wv, 32);
        attn_kernel<<<dim3(DD / TD, HH / TH, 16), b2, 0, s2>>>(rel_h, rel_w, rel_d, out, 32);

        cudaEventRecord(eJoin, s2);
        cudaStreamWaitEvent(0, eJoin, 0);
    } else {
        qkv_kernel<32><<<NV / 2 / 256, 256>>>(x, Wq, Wk, Wv, 0);
        qkv_kernel<16><<<NV / 2 / 256, 256>>>(x, Wq, Wk, Wv, 32);
        attn_kernel<<<dim3(DD / TD, HH / TH, 32), b2>>>(rel_h, rel_w, rel_d, out, 0);
        attn_kernel<<<dim3(DD / TD, HH / TH, 16), b2>>>(rel_h, rel_w, rel_d, out, 32);
    }
}

// round 10
// speedup vs baseline: 1.5510x; 1.1095x over previous
#include <cuda_runtime.h>

#define DD 24
#define HH 48
#define WW 64
#define NV (DD*HH*WW)        /* 73728 interior voxels */
#define CIN 32
#define COUT 48
#define OHALF 24             /* channels per qkv block (gridDim.y = 2) */

#define TD 4
#define TH 8
#define SROW 68                        /* padded smem row stride (floats) */
#define NROWS ((TD+2)*(TH+2))          /* 60 */

// scratch (allocation-free rule: __device__ globals)
__device__ float g_q[COUT * NV];
__device__ float g_k[COUT * NV];
__device__ float g_v[COUT * NV];

typedef unsigned long long u64;
__device__ __forceinline__ u64 fma2(u64 a, u64 b, u64 c) {
    u64 d; asm("fma.rn.f32x2 %0,%1,%2,%3;" : "=l"(d) : "l"(a), "l"(b), "l"(c));
    return d;
}
__device__ __forceinline__ u64 add2(u64 a, u64 b) {
    u64 d; asm("add.rn.f32x2 %0,%1,%2;" : "=l"(d) : "l"(a), "l"(b));
    return d;
}
__device__ __forceinline__ float ex2f(float x) {
    float y; asm("ex2.approx.ftz.f32 %0, %1;" : "=f"(y) : "f"(x)); return y;
}
__device__ __forceinline__ float rcpf(float x) {
    float y; asm("rcp.approx.ftz.f32 %0, %1;" : "=f"(y) : "f"(x)); return y;
}

// ---------------------------------------------------------------------------
// Fused QKV (R7-measured ~21us): one thread = one voxel pair x 24 channels;
// packed f32x2 math, LDS.128 weights.
// ---------------------------------------------------------------------------
__global__ __launch_bounds__(256)
void qkv_kernel(const float* __restrict__ x,
                const float* __restrict__ Wq,
                const float* __restrict__ Wk,
                const float* __restrict__ Wv) {
    __shared__ u64 swq[OHALF * CIN];
    __shared__ u64 swk[OHALF * CIN];
    __shared__ u64 swv[OHALF * CIN];

    const int ob = blockIdx.y * OHALF;
    for (int i = threadIdx.x; i < OHALF * CIN; i += 256) {
        const int gi = ob * CIN + i;
        float a = Wq[gi], b = Wk[gi], c = Wv[gi];
        u64 pa, pb, pc;
        asm("mov.b64 %0,{%1,%1};" : "=l"(pa) : "f"(a));
        asm("mov.b64 %0,{%1,%1};" : "=l"(pb) : "f"(b));
        asm("mov.b64 %0,{%1,%1};" : "=l"(pc) : "f"(c));
        swq[i] = pa; swk[i] = pb; swv[i] = pc;
    }
    __syncthreads();

    const int t = blockIdx.x * 256 + threadIdx.x;   // 0..36863
    const int v0 = t * 2;

    u64 xs[CIN];
    #pragma unroll
    for (int c = 0; c < CIN; c++)
        xs[c] = *(const u64*)(x + c * NV + v0);

    float* __restrict__ gq = g_q + ob * NV + v0;
    float* __restrict__ gk = g_k + ob * NV + v0;
    float* __restrict__ gv = g_v + ob * NV + v0;

    #pragma unroll 4
    for (int o = 0; o < OHALF; o++) {
        u64 qa = 0, qb = 0, ka = 0, kb = 0, va = 0, vb = 0;
        #pragma unroll
        for (int c = 0; c < CIN; c += 2) {
            const u64 x0 = xs[c], x1 = xs[c + 1];
            const ulonglong2 wq = *(const ulonglong2*)&swq[o * CIN + c];
            const ulonglong2 wk = *(const ulonglong2*)&swk[o * CIN + c];
            const ulonglong2 wv = *(const ulonglong2*)&swv[o * CIN + c];
            qa = fma2(wq.x, x0, qa);  qb = fma2(wq.y, x1, qb);
            ka = fma2(wk.x, x0, ka);  kb = fma2(wk.y, x1, kb);
            va = fma2(wv.x, x0, va);  vb = fma2(wv.y, x1, vb);
        }
        *(u64*)(gq + o * NV) = add2(qa, qb);
        *(u64*)(gk + o * NV) = add2(ka, kb);
        *(u64*)(gv + o * NV) = add2(va, vb);
    }
}

// ---------------------------------------------------------------------------
// Pass 2: per-channel attention, 4 outputs/thread, tile 4x8x64 (512 threads).
// Halo load: div-free, aligned LDG.128; w-halo columns are globally OOB ->
// zero-filled, no column predicate.
// ---------------------------------------------------------------------------
template<int GRP>
__device__ __forceinline__ void attn_core(const float* __restrict__ sk,
                                          const float* __restrict__ sv,
                                          const float qs[4],
                                          const float qb[3][4],
                                          int rbase, int w0,
                                          float num[4], float den[4]) {
    #pragma unroll
    for (int kd = 0; kd < 3; kd++) {
        #pragma unroll
        for (int kh = 0; kh < 3; kh++) {
            const int rb = rbase + (kd * (TH + 2) + kh) * SROW + w0;
            const float4 ka = *(const float4*)(sk + rb);
            const float2 kc = *(const float2*)(sk + rb + 4);
            const float4 va = *(const float4*)(sv + rb);
            const float2 vc = *(const float2*)(sv + rb + 4);
            const float kk[6] = {ka.x, ka.y, ka.z, ka.w, kc.x, kc.y};
            const float vv[6] = {va.x, va.y, va.z, va.w, vc.x, vc.y};
            #pragma unroll
            for (int kw = 0; kw < 3; kw++) {
                const int sel = (GRP == 0) ? kw : ((GRP == 1) ? kd : kh);
                #pragma unroll
                for (int wi = 0; wi < 4; wi++) {
                    const float arg = fmaf(qs[wi], kk[wi + kw], qb[sel][wi]);
                    const float ex  = ex2f(arg);
                    den[wi] += ex;
                    num[wi] = fmaf(ex, vv[wi + kw], num[wi]);
                }
            }
        }
    }
}

__global__ __launch_bounds__(512, 3)
void attn_kernel(const float* __restrict__ rel_h,
                 const float* __restrict__ rel_w,
                 const float* __restrict__ rel_d,
                 float* __restrict__ out) {
    __shared__ float sk[NROWS * SROW];
    __shared__ float sv[NROWS * SROW];

    const int o  = blockIdx.z;
    const int d0 = blockIdx.x * TD;
    const int h0 = blockIdx.y * TH;
    const int tid = threadIdx.x + (threadIdx.y << 4) + (threadIdx.z << 7);

    // ---- hoisted gmem loads (overlap with halo fill) ----
    const int w0 = threadIdx.x << 2;
    const int hl = threadIdx.y;
    const int dl = threadIdx.z;
    const int vox0 = ((d0 + dl) * HH + (h0 + hl)) * WW + w0;

    const float4 q4 = *(const float4*)(g_q + o * NV + vox0);
    const int grp = o >> 4, ci = o & 15;
    const float* rel = (grp == 0) ? (rel_d + ci * 3)
                     : (grp == 1) ? (rel_h + ci * 3)
                                  : (rel_w + ci * 3);
    const float b0 = rel[0], b1 = rel[1], b2 = rel[2];

    const float L2E = 1.4426950408889634f;
    float qs[4] = {q4.x * L2E, q4.y * L2E, q4.z * L2E, q4.w * L2E};
    float qb[3][4];
    #pragma unroll
    for (int wi = 0; wi < 4; wi++) {
        qb[0][wi] = qs[wi] * b0;
        qb[1][wi] = qs[wi] * b1;
        qb[2][wi] = qs[wi] * b2;
    }

    // ---- halo load ----
    // w-halo (smem cols 0 and 65) is globally out-of-bounds: always zero.
    if (tid < NROWS * 2) {
        const int r = tid >> 1;
        const int c = (tid & 1) ? 65 : 0;
        sk[r * SROW + c] = 0.f;
        sv[r * SROW + c] = 0.f;
    }
    // main region: row r (0..59), 64 floats per row, aligned LDG.128.
    {
        const int cbase = o * NV;
        const int cx = (tid & 15) << 2;     // w = cx..cx+3
        const int ry = tid >> 4;            // 0..31
        #pragma unroll
        for (int rr = 0; rr < 2; rr++) {
            const int r = ry + rr * 32;
            if (r < NROWS) {
                const int dd = r / (TH + 2);              // mul-shift
                const int hh = r - dd * (TH + 2);
                const int d = d0 + dd - 1;
                const int h = h0 + hh - 1;
                float4 kq = {0.f, 0.f, 0.f, 0.f};
                float4 vq = {0.f, 0.f, 0.f, 0.f};
                if (((unsigned)d < DD) & ((unsigned)h < HH)) {
                    const int g = cbase + (d * HH + h) * WW + cx;
                    kq = *(const float4*)(g_k + g);
                    vq = *(const float4*)(g_v + g);
                }
                const int s = r * SROW + 1 + cx;
                sk[s + 0] = kq.x; sk[s + 1] = kq.y; sk[s + 2] = kq.z; sk[s + 3] = kq.w;
                sv[s + 0] = vq.x; sv[s + 1] = vq.y; sv[s + 2] = vq.z; sv[s + 3] = vq.w;
            }
        }
    }
    __syncthreads();

    const int rbase = (dl * (TH + 2) + hl) * SROW;

    float num[4] = {0.f, 0.f, 0.f, 0.f};
    float den[4] = {0.f, 0.f, 0.f, 0.f};

    if (grp == 0)      attn_core<0>(sk, sv, qs, qb, rbase, w0, num, den);
    else if (grp == 1) attn_core<1>(sk, sv, qs, qb, rbase, w0, num, den);
    else               attn_core<2>(sk, sv, qs, qb, rbase, w0, num, den);

    float4 r;
    r.x = num[0] * rcpf(den[0]);
    r.y = num[1] * rcpf(den[1]);
    r.z = num[2] * rcpf(den[2]);
    r.w = num[3] * rcpf(den[3]);
    *(float4*)(out + o * NV + vox0) = r;
}

extern "C" void kernel_launch(void* const* d_in, const int* in_sizes, int n_in,
                              void* d_out, int out_size) {
    const float* x     = (const float*)d_in[0];
    const float* Wq    = (const float*)d_in[1];
    const float* Wk    = (const float*)d_in[2];
    const float* Wv    = (const float*)d_in[3];
    const float* rel_h = (const float*)d_in[4];
    const float* rel_w = (const float*)d_in[5];
    const float* rel_d = (const float*)d_in[6];
    float* out = (float*)d_out;

    dim3 g1(NV / 2 / 256, 2);
    qkv_kernel<<<g1, 256>>>(x, Wq, Wk, Wv);

    dim3 g2(DD / TD, HH / TH, COUT);
    dim3 b2(16, TH, TD);
    attn_kernel<<<g2, b2>>>(rel_h, rel_w, rel_d, out);
}